// round 5
// baseline (speedup 1.0000x reference)
#include <cuda_runtime.h>
#include <cuda_fp16.h>
#include <cstdint>

// ---------------------------------------------------------------------------
// out[n,o] = sum_s attn[s] * (X[s] @ W[s])[n,o] + bias[o]
// One GEMM: A[m,k]=X[k/128][m][k%128] (M=200000,K=1024), Bh fp16 (N=128).
// R5: cp.async.bulk + mbarrier (kills LDGSTS issue bottleneck).
//     B pre-swizzled & stage-major in global so one 8KB bulk op per stage.
// ---------------------------------------------------------------------------

#define NROWS    200000
#define KTOT     1024
#define BLOCK_M  128
#define NSTAGES  4
#define A_PITCH  144                         // 2-way-conflict-max LDS pitch

#define A_SMEM_BYTES (BLOCK_M * A_PITCH)     // 18432
#define A_TX_BYTES   (BLOCK_M * 128)         // 16384 actually copied
#define B_BYTES      8192                    // 128 o x 32 k fp16
#define STAGE_BYTES  (A_SMEM_BYTES + B_BYTES)        // 26624
#define TX_BYTES     (A_TX_BYTES + B_BYTES)          // 24576

#define SMEM_BIAS    0
#define SMEM_MBAR    512
#define SMEM_STAGE0  1024
#define SMEM_TOTAL   (SMEM_STAGE0 + NSTAGES * STAGE_BYTES)  // 107520 -> 2 CTAs/SM

// B: stage-major, attn-folded, fp16, PRE-SWIZZLED for conflict-free ldmatrix.
// Element (t, o, kk) lives at t*4096 + o*32 + ((kk>>3) ^ ((o>>1)&3))*8 + (kk&7).
__device__ __half g_Wh[128 * KTOT];

// ---- helpers ---------------------------------------------------------------

__device__ __forceinline__ uint32_t smem_u32(const void* p) {
    uint32_t a;
    asm("{ .reg .u64 t; cvta.to.shared.u64 t, %1; cvt.u32.u64 %0, t; }"
        : "=r"(a) : "l"(p));
    return a;
}

__device__ __forceinline__ void ldsm_x4(uint32_t* r, uint32_t addr) {
    asm volatile("ldmatrix.sync.aligned.m8n8.x4.shared.b16 {%0,%1,%2,%3}, [%4];"
                 : "=r"(r[0]), "=r"(r[1]), "=r"(r[2]), "=r"(r[3]) : "r"(addr));
}

__device__ __forceinline__ void mma_f16(float* c, const uint32_t* a,
                                        uint32_t b0, uint32_t b1) {
    asm volatile(
        "mma.sync.aligned.m16n8k16.row.col.f32.f16.f16.f32 "
        "{%0,%1,%2,%3}, {%4,%5,%6,%7}, {%8,%9}, {%0,%1,%2,%3};"
        : "+f"(c[0]), "+f"(c[1]), "+f"(c[2]), "+f"(c[3])
        : "r"(a[0]), "r"(a[1]), "r"(a[2]), "r"(a[3]), "r"(b0), "r"(b1));
}

// 2 consecutive f32 at (row w, col cl) from A tile (linear, pitch 144) -> f16x2
__device__ __forceinline__ uint32_t a_pair_f16(uint32_t aB, int w, int cl) {
    uint32_t addr = aB + (uint32_t)(w * A_PITCH + cl * 4);
    float x, y;
    asm("ld.shared.v2.f32 {%0,%1}, [%2];" : "=f"(x), "=f"(y) : "r"(addr));
    uint32_t d;
    asm("cvt.rn.f16x2.f32 %0, %1, %2;" : "=r"(d) : "f"(y), "f"(x));
    return d;
}

__device__ __forceinline__ void mbar_wait(uint32_t mbar, uint32_t parity) {
    asm volatile(
        "{\n\t"
        ".reg .pred P1;\n\t"
        "WAIT_LOOP_%=:\n\t"
        "mbarrier.try_wait.parity.acquire.cta.shared::cta.b64 P1, [%0], %1, 0x989680;\n\t"
        "@P1 bra.uni WAIT_DONE_%=;\n\t"
        "bra.uni WAIT_LOOP_%=;\n\t"
        "WAIT_DONE_%=:\n\t"
        "}"
        :: "r"(mbar), "r"(parity) : "memory");
}

// Warp 0 only: issue bulk copies for K-chunk t into ring slot.
__device__ __forceinline__ void issue_stage(const float* __restrict__ X,
                                            uint32_t sb, int slot, int t,
                                            int m0, int lane) {
    const uint32_t mbar = sb + SMEM_MBAR + slot * 8;
    const uint32_t aB   = sb + SMEM_STAGE0 + slot * STAGE_BYTES;
    if (lane == 0)
        asm volatile("mbarrier.arrive.expect_tx.shared.b64 _, [%0], %1;"
                     :: "r"(mbar), "r"((uint32_t)TX_BYTES) : "memory");
    __syncwarp();

    const int s  = t >> 2;
    const int i0 = (t & 3) << 5;
    const float* gA = X + ((size_t)s * NROWS + m0) * 128 + i0;

    #pragma unroll
    for (int i = 0; i < 4; i++) {
        int r = lane + 32 * i;
        const void* src = ((m0 + r) < NROWS) ? (const void*)(gA + (size_t)r * 128)
                                             : (const void*)X;   // safe dummy row
        asm volatile(
            "cp.async.bulk.shared::cta.global.mbarrier::complete_tx::bytes "
            "[%0], [%1], %2, [%3];"
            :: "r"(aB + (uint32_t)(r * A_PITCH)), "l"(src), "r"(128u), "r"(mbar)
            : "memory");
    }
    if (lane == 0) {
        const void* srcB = (const void*)(g_Wh + (size_t)t * 4096);
        asm volatile(
            "cp.async.bulk.shared::cta.global.mbarrier::complete_tx::bytes "
            "[%0], [%1], %2, [%3];"
            :: "r"(aB + (uint32_t)A_SMEM_BYTES), "l"(srcB), "r"((uint32_t)B_BYTES),
               "r"(mbar)
            : "memory");
    }
}

// ---- prep: stage-major, pre-swizzled fp16 B ---------------------------------

__global__ void prep_kernel(const float* __restrict__ W, const float* __restrict__ attn) {
    int idx = blockIdx.x * 256 + threadIdx.x;
    if (idx >= 128 * KTOT) return;
    int o = idx >> 10;
    int k = idx & (KTOT - 1);
    int s = k >> 7;
    int i = k & 127;
    float v = attn[s] * W[((s << 7) + i) * 128 + o];
    int t  = k >> 5;
    int kk = k & 31;
    int dst = t * 4096 + o * 32 + (((kk >> 3) ^ ((o >> 1) & 3)) << 3) + (kk & 7);
    g_Wh[dst] = __float2half_rn(v);
}

// ---- main GEMM --------------------------------------------------------------

__global__ void __launch_bounds__(256, 2)
mgc_kernel(const float* __restrict__ X, const float* __restrict__ bias,
           float* __restrict__ out) {
    extern __shared__ char smem[];
    const uint32_t sb  = smem_u32(smem);
    const int tid = threadIdx.x;
    const int lid = tid & 31;
    const int wid = tid >> 5;
    const int wm  = wid >> 1;          // 0..3  (32-row slices)
    const int wn  = wid & 1;           // 0..1  (64-col slices)
    const int m0  = blockIdx.x * BLOCK_M;

    if (tid < 128)
        reinterpret_cast<float*>(smem)[tid] = bias[tid];

    if (tid == 0) {
        #pragma unroll
        for (int j = 0; j < NSTAGES; j++)
            asm volatile("mbarrier.init.shared.b64 [%0], 1;"
                         :: "r"(sb + SMEM_MBAR + j * 8) : "memory");
        asm volatile("fence.proxy.async.shared::cta;" ::: "memory");
    }
    __syncthreads();

    // fragment geometry
    const int arow = lid >> 2;                           // A frag row within 8
    const int ac2  = (lid & 3) * 2;                      // A frag col pair base
    const int blrow = wn * 64 + ((lid >> 4) & 1) * 8 + (lid & 7);  // B x4 row
    const int blc   = (lid >> 3) & 1;                    // B k-chunk selector

    float acc[2][8][4];
    #pragma unroll
    for (int mt = 0; mt < 2; mt++)
        #pragma unroll
        for (int nt = 0; nt < 8; nt++)
            #pragma unroll
            for (int v = 0; v < 4; v++) acc[mt][nt][v] = 0.f;

    // prologue: fill ring
    if (wid == 0) {
        #pragma unroll
        for (int p = 0; p < NSTAGES; p++)
            issue_stage(X, sb, p, p, m0, lid);
    }

    const int NITER = KTOT / 32;   // 32
    for (int t = 0; t < NITER; t++) {
        const int slot = t & (NSTAGES - 1);
        mbar_wait(sb + SMEM_MBAR + slot * 8, (t >> 2) & 1);

        const uint32_t aB = sb + SMEM_STAGE0 + slot * STAGE_BYTES;
        const uint32_t bB = aB + A_SMEM_BYTES;

        #pragma unroll
        for (int j = 0; j < 2; j++) {            // two k16 steps
            // B fragments: 4 x ldsm.x4 covers 8 n-tiles x k16
            uint32_t bf[8][2];
            #pragma unroll
            for (int ntp = 0; ntp < 4; ntp++) {
                int n = blrow + ntp * 16;
                int c = 2 * j + blc;
                uint32_t addr = bB + (uint32_t)(n * 64 + ((c ^ ((n >> 1) & 3)) << 4));
                uint32_t q[4];
                ldsm_x4(q, addr);
                bf[2 * ntp][0] = q[0];  bf[2 * ntp][1] = q[1];
                bf[2 * ntp + 1][0] = q[2];  bf[2 * ntp + 1][1] = q[3];
            }
            // A fragments: f32 smem -> f16 regs
            uint32_t af[2][4];
            #pragma unroll
            for (int mt = 0; mt < 2; mt++) {
                int R  = wm * 32 + mt * 16;
                int cl = j * 16 + ac2;
                af[mt][0] = a_pair_f16(aB, R + arow,     cl);
                af[mt][1] = a_pair_f16(aB, R + arow + 8, cl);
                af[mt][2] = a_pair_f16(aB, R + arow,     cl + 8);
                af[mt][3] = a_pair_f16(aB, R + arow + 8, cl + 8);
            }
            #pragma unroll
            for (int mt = 0; mt < 2; mt++)
                #pragma unroll
                for (int nt = 0; nt < 8; nt++)
                    mma_f16(acc[mt][nt], af[mt], bf[nt][0], bf[nt][1]);
        }

        __syncthreads();                          // all warps done with slot
        if (wid == 0 && t + NSTAGES < NITER)
            issue_stage(X, sb, slot, t + NSTAGES, m0, lid);
    }

    // ---- epilogue: acc + bias -> out ----------------------------------------
    const float* bs = reinterpret_cast<const float*>(smem);
    const int tig = lid & 3;
    const int g   = lid >> 2;

    float2 bv[8];
    #pragma unroll
    for (int nt = 0; nt < 8; nt++) {
        int c = wn * 64 + nt * 8 + 2 * tig;
        bv[nt].x = bs[c];
        bv[nt].y = bs[c + 1];
    }

    #pragma unroll
    for (int mt = 0; mt < 2; mt++) {
        int mrow = m0 + wm * 32 + mt * 16 + g;
        #pragma unroll
        for (int half = 0; half < 2; half++) {       // rows g and g+8
            int m = mrow + half * 8;
            if (m < NROWS) {
                float* po = out + (size_t)m * 128 + wn * 64;
                #pragma unroll
                for (int nt = 0; nt < 8; nt++) {
                    float2 v;
                    v.x = acc[mt][nt][2 * half + 0] + bv[nt].x;
                    v.y = acc[mt][nt][2 * half + 1] + bv[nt].y;
                    *reinterpret_cast<float2*>(po + nt * 8 + 2 * tig) = v;
                }
            }
        }
    }
}

// ---- launch -----------------------------------------------------------------

extern "C" void kernel_launch(void* const* d_in, const int* in_sizes, int n_in,
                              void* d_out, int out_size) {
    const float* X    = (const float*)d_in[0];   // (8, 200000, 128) f32
    const float* W    = (const float*)d_in[1];   // (8, 128, 128)    f32
    const float* attn = (const float*)d_in[2];   // (8,)             f32
    const float* bias = (const float*)d_in[3];   // (128,)           f32
    float* out = (float*)d_out;                  // (200000, 128)    f32

    cudaFuncSetAttribute(mgc_kernel, cudaFuncAttributeMaxDynamicSharedMemorySize,
                         SMEM_TOTAL);

    prep_kernel<<<(128 * KTOT + 255) / 256, 256>>>(W, attn);

    int grid = (NROWS + BLOCK_M - 1) / BLOCK_M;   // 1563
    mgc_kernel<<<grid, 256, SMEM_TOTAL>>>(X, bias, out);
}

// round 6
// speedup vs baseline: 3.7595x; 3.7595x over previous
#include <cuda_runtime.h>
#include <cuda_fp16.h>
#include <cstdint>

// ---------------------------------------------------------------------------
// out[n,o] = sum_s attn[s] * (X[s] @ W[s])[n,o] + bias[o]
// R6: stage = one support s. A = contiguous 64KB -> ONE cp.async.bulk.
//     B = 32KB stage-major pre-swizzled fp16 -> ONE bulk. 2-slot ring.
//     Per-k32 fp32->fp16 conversion into 8KB ping-pong staging; ldmatrix feed.
// ---------------------------------------------------------------------------

#define NROWS    200000
#define BLOCK_M  128
#define NSUP     8

#define A_FP32_BYTES 65536                   // 128 rows x 128 f32
#define B_BYTES      32768                   // 128 o x 128 i f16 (pre-swizzled)
#define SLOT_BYTES   (A_FP32_BYTES + B_BYTES)    // 98304

#define SMEM_MBAR    0                       // 2 x 8B
#define SMEM_STG     1024                    // 2 x 8192 staging
#define SMEM_SLOT0   (1024 + 16384)          // 17408
#define SMEM_TOTAL   (SMEM_SLOT0 + 2 * SLOT_BYTES)   // 214016

// B: stage-major fp16, attn-folded, swizzled: (s,o,i) ->
//   s*16384 + o*128 + ((i>>3) ^ (o&7))*8 + (i&7)
__device__ __half g_Wh[NSUP * 128 * 128];

// ---- helpers ---------------------------------------------------------------

__device__ __forceinline__ uint32_t smem_u32(const void* p) {
    uint32_t a;
    asm("{ .reg .u64 t; cvta.to.shared.u64 t, %1; cvt.u32.u64 %0, t; }"
        : "=r"(a) : "l"(p));
    return a;
}

__device__ __forceinline__ void ldsm_x4(uint32_t* r, uint32_t addr) {
    asm volatile("ldmatrix.sync.aligned.m8n8.x4.shared.b16 {%0,%1,%2,%3}, [%4];"
                 : "=r"(r[0]), "=r"(r[1]), "=r"(r[2]), "=r"(r[3]) : "r"(addr));
}

__device__ __forceinline__ void mma_f16(float* c, const uint32_t* a,
                                        uint32_t b0, uint32_t b1) {
    asm volatile(
        "mma.sync.aligned.m16n8k16.row.col.f32.f16.f16.f32 "
        "{%0,%1,%2,%3}, {%4,%5,%6,%7}, {%8,%9}, {%0,%1,%2,%3};"
        : "+f"(c[0]), "+f"(c[1]), "+f"(c[2]), "+f"(c[3])
        : "r"(a[0]), "r"(a[1]), "r"(a[2]), "r"(a[3]), "r"(b0), "r"(b1));
}

__device__ __forceinline__ void mbar_wait(uint32_t mbar, uint32_t parity) {
    asm volatile(
        "{\n\t"
        ".reg .pred P1;\n\t"
        "WAIT_LOOP_%=:\n\t"
        "mbarrier.try_wait.parity.acquire.cta.shared::cta.b64 P1, [%0], %1, 0x989680;\n\t"
        "@P1 bra.uni WAIT_DONE_%=;\n\t"
        "bra.uni WAIT_LOOP_%=;\n\t"
        "WAIT_DONE_%=:\n\t"
        "}"
        :: "r"(mbar), "r"(parity) : "memory");
}

// single-thread: issue the 2 bulk copies for support s into slot
__device__ __forceinline__ void issue_stage(const float* __restrict__ X,
                                            uint32_t sb, int slot, int s,
                                            int m0, uint32_t a_bytes) {
    const uint32_t mbar = sb + SMEM_MBAR + slot * 8;
    const uint32_t aDst = sb + SMEM_SLOT0 + slot * SLOT_BYTES;
    asm volatile("mbarrier.arrive.expect_tx.shared.b64 _, [%0], %1;"
                 :: "r"(mbar), "r"(a_bytes + (uint32_t)B_BYTES) : "memory");
    const float* gA = X + ((size_t)s * NROWS + m0) * 128;
    asm volatile(
        "cp.async.bulk.shared::cta.global.mbarrier::complete_tx::bytes "
        "[%0], [%1], %2, [%3];"
        :: "r"(aDst), "l"(gA), "r"(a_bytes), "r"(mbar) : "memory");
    const void* gB = (const void*)(g_Wh + (size_t)s * 16384);
    asm volatile(
        "cp.async.bulk.shared::cta.global.mbarrier::complete_tx::bytes "
        "[%0], [%1], %2, [%3];"
        :: "r"(aDst + (uint32_t)A_FP32_BYTES), "l"(gB), "r"((uint32_t)B_BYTES),
           "r"(mbar) : "memory");
}

// ---- prep: stage-major, ldmatrix-swizzled fp16 B ----------------------------

__global__ void prep_kernel(const float* __restrict__ W, const float* __restrict__ attn) {
    int idx = blockIdx.x * 256 + threadIdx.x;
    if (idx >= NSUP * 128 * 128) return;
    int s = idx >> 14;
    int o = (idx >> 7) & 127;
    int i = idx & 127;
    float v = attn[s] * W[((s << 7) + i) * 128 + o];
    int dst = s * 16384 + o * 128 + ((((i >> 3) ^ (o & 7))) << 3) + (i & 7);
    g_Wh[dst] = __float2half_rn(v);
}

// ---- main GEMM --------------------------------------------------------------

__global__ void __launch_bounds__(256, 1)
mgc_kernel(const float* __restrict__ X, const float* __restrict__ bias,
           float* __restrict__ out) {
    extern __shared__ char smem[];
    const uint32_t sb  = smem_u32(smem);
    const int tid = threadIdx.x;
    const int lid = tid & 31;
    const int wid = tid >> 5;
    const int wm  = wid >> 1;          // 0..3  (32-row slices)
    const int wn  = wid & 1;           // 0..1  (64-col slices)
    const int m0  = blockIdx.x * BLOCK_M;

    const uint32_t a_bytes =
        (uint32_t)((NROWS - m0 >= BLOCK_M ? BLOCK_M : NROWS - m0) * 512);

    if (tid == 0) {
        asm volatile("mbarrier.init.shared.b64 [%0], 1;" :: "r"(sb + SMEM_MBAR) : "memory");
        asm volatile("mbarrier.init.shared.b64 [%0], 1;" :: "r"(sb + SMEM_MBAR + 8) : "memory");
        asm volatile("fence.proxy.async.shared::cta;" ::: "memory");
    }
    __syncthreads();
    if (tid == 0) {
        issue_stage(X, sb, 0, 0, m0, a_bytes);
        issue_stage(X, sb, 1, 1, m0, a_bytes);
    }

    // ldmatrix lane geometry (precomputed)
    const int rA_base = wm * 32 + (lid & 15);       // + mt*16
    const int a_usel  = (lid >> 4) & 1;             // unit +0/+1
    const int o_base  = wn * 64 + (lid & 7) + ((lid >> 4) & 1) * 8;  // + 16*p
    const int b_usel  = (lid >> 3) & 1;

    float acc[2][8][4];
    #pragma unroll
    for (int mt = 0; mt < 2; mt++)
        #pragma unroll
        for (int nt = 0; nt < 8; nt++)
            #pragma unroll
            for (int v = 0; v < 4; v++) acc[mt][nt][v] = 0.f;

    for (int s = 0; s < NSUP; s++) {
        const int slot = s & 1;
        mbar_wait(sb + SMEM_MBAR + slot * 8, (s >> 1) & 1);

        const uint32_t aSlot = sb + SMEM_SLOT0 + slot * SLOT_BYTES;
        const uint32_t bSlot = aSlot + A_FP32_BYTES;

        #pragma unroll
        for (int c = 0; c < 4; c++) {               // k32 chunks
            const uint32_t stg = sb + SMEM_STG + (c & 1) * 8192;

            // ---- convert 128 rows x 32 f32 -> fp16 staging (swizzled) ----
            #pragma unroll
            for (int i = 0; i < 4; i++) {
                int f4  = tid + 256 * i;
                int row = f4 >> 3, fc = f4 & 7;
                float x, y, z, w;
                asm("ld.shared.v4.f32 {%0,%1,%2,%3}, [%4];"
                    : "=f"(x), "=f"(y), "=f"(z), "=f"(w)
                    : "r"(aSlot + (uint32_t)(row * 512 + c * 128 + fc * 16)));
                uint32_t h0, h1;
                asm("cvt.rn.f16x2.f32 %0, %1, %2;" : "=r"(h0) : "f"(y), "f"(x));
                asm("cvt.rn.f16x2.f32 %0, %1, %2;" : "=r"(h1) : "f"(w), "f"(z));
                int phys = (fc >> 1) ^ ((row >> 1) & 3);
                asm volatile("st.shared.v2.b32 [%0], {%1,%2};"
                    :: "r"(stg + (uint32_t)(row * 64 + phys * 16 + (fc & 1) * 8)),
                       "r"(h0), "r"(h1) : "memory");
            }
            __syncthreads();

            // ---- 2 x k16 MMA steps --------------------------------------
            #pragma unroll
            for (int jl = 0; jl < 2; jl++) {
                uint32_t af[2][4];
                #pragma unroll
                for (int mt = 0; mt < 2; mt++) {
                    int r = rA_base + mt * 16;
                    int u = 2 * jl + a_usel;
                    uint32_t addr = stg + (uint32_t)(r * 64 +
                                       ((u ^ ((r >> 1) & 3)) << 4));
                    ldsm_x4(af[mt], addr);
                }
                uint32_t bq[4][4];
                #pragma unroll
                for (int p = 0; p < 4; p++) {
                    int o = o_base + 16 * p;
                    int u = 4 * c + 2 * jl + b_usel;
                    uint32_t addr = bSlot + (uint32_t)(o * 256 +
                                        ((u ^ (o & 7)) << 4));
                    ldsm_x4(bq[p], addr);
                }
                #pragma unroll
                for (int mt = 0; mt < 2; mt++)
                    #pragma unroll
                    for (int p = 0; p < 4; p++) {
                        mma_f16(acc[mt][2 * p],     af[mt], bq[p][0], bq[p][1]);
                        mma_f16(acc[mt][2 * p + 1], af[mt], bq[p][2], bq[p][3]);
                    }
            }
        }

        __syncthreads();                 // slot fully consumed
        if (tid == 0 && s + 2 < NSUP)
            issue_stage(X, sb, slot, s + 2, m0, a_bytes);
    }

    // ---- epilogue: acc + bias -> out ----------------------------------------
    const int tig = lid & 3;
    const int g   = lid >> 2;

    float2 bv[8];
    #pragma unroll
    for (int nt = 0; nt < 8; nt++) {
        int cidx = wn * 64 + nt * 8 + 2 * tig;
        bv[nt].x = __ldg(&bias[cidx]);
        bv[nt].y = __ldg(&bias[cidx + 1]);
    }

    #pragma unroll
    for (int mt = 0; mt < 2; mt++) {
        int mrow = m0 + wm * 32 + mt * 16 + g;
        #pragma unroll
        for (int half = 0; half < 2; half++) {
            int m = mrow + half * 8;
            if (m < NROWS) {
                float* po = out + (size_t)m * 128 + wn * 64;
                #pragma unroll
                for (int nt = 0; nt < 8; nt++) {
                    float2 v;
                    v.x = acc[mt][nt][2 * half + 0] + bv[nt].x;
                    v.y = acc[mt][nt][2 * half + 1] + bv[nt].y;
                    *reinterpret_cast<float2*>(po + nt * 8 + 2 * tig) = v;
                }
            }
        }
    }
}

// ---- launch -----------------------------------------------------------------

extern "C" void kernel_launch(void* const* d_in, const int* in_sizes, int n_in,
                              void* d_out, int out_size) {
    const float* X    = (const float*)d_in[0];   // (8, 200000, 128) f32
    const float* W    = (const float*)d_in[1];   // (8, 128, 128)    f32
    const float* attn = (const float*)d_in[2];   // (8,)             f32
    const float* bias = (const float*)d_in[3];   // (128,)           f32
    float* out = (float*)d_out;                  // (200000, 128)    f32

    cudaFuncSetAttribute(mgc_kernel, cudaFuncAttributeMaxDynamicSharedMemorySize,
                         SMEM_TOTAL);

    prep_kernel<<<(NSUP * 128 * 128 + 255) / 256, 256>>>(W, attn);

    int grid = (NROWS + BLOCK_M - 1) / BLOCK_M;   // 1563
    mgc_kernel<<<grid, 256, SMEM_TOTAL>>>(X, bias, out);
}